// round 11
// baseline (speedup 1.0000x reference)
#include <cuda_runtime.h>
#include <cstdint>
#include <math.h>

#define T_LEN  2048
#define D_EMB  300
#define H_DIM  256
#define G4     1024
#define K_TAGS 48
#define START_TAG 46
#define STOP_TAG  47

// ---------------- scratch (device globals; no allocation) ----------------
__device__ float g_x[T_LEN * D_EMB];        // gathered embeddings [T, D]
__device__ float g_xg[2][T_LEN * G4];       // input projections per dir [T, 4H]
__device__ float g_hs[2][T_LEN * H_DIM];    // hidden states per dir, time-aligned
__device__ float g_feats[T_LEN * K_TAGS];   // emission features [T, K]

// ---------------- f32x2 helpers ----------------
__device__ __forceinline__ unsigned long long pack2(float lo, float hi) {
    unsigned long long r;
    asm("mov.b64 %0, {%1,%2};" : "=l"(r) : "f"(lo), "f"(hi));
    return r;
}
__device__ __forceinline__ void unpack2(unsigned long long v, float& lo, float& hi) {
    asm("mov.b64 {%0,%1}, %2;" : "=f"(lo), "=f"(hi) : "l"(v));
}
__device__ __forceinline__ unsigned long long mul2(unsigned long long a, unsigned long long b) {
    unsigned long long d;
    asm("mul.rn.f32x2 %0, %1, %2;" : "=l"(d) : "l"(a), "l"(b));
    return d;
}
__device__ __forceinline__ unsigned long long fma2(unsigned long long a, unsigned long long b,
                                                   unsigned long long c) {
    unsigned long long d;
    asm("fma.rn.f32x2 %0, %1, %2, %3;" : "=l"(d) : "l"(a), "l"(b), "l"(c));
    return d;
}

// ---------------- 1) embedding gather ----------------
__global__ void gather_kernel(const int* __restrict__ sent,
                              const float* __restrict__ E) {
    int idx = blockIdx.x * blockDim.x + threadIdx.x;
    int total = T_LEN * D_EMB;
    for (; idx < total; idx += gridDim.x * blockDim.x) {
        int t = idx / D_EMB;
        int d = idx - t * D_EMB;
        long long row = sent[t];
        g_x[idx] = E[row * D_EMB + d];
    }
}

// ---------------- 2) xg GEMM: [T,D] @ [4H,D]^T + (b_ih + b_hh) ----------------
#define BM 64
#define BN 64
#define BK 12
__global__ void xg_gemm_kernel(const float* __restrict__ Wf,
                               const float* __restrict__ Wb,
                               const float* __restrict__ bihf,
                               const float* __restrict__ bhhf,
                               const float* __restrict__ bihb,
                               const float* __restrict__ bhhb) {
    int dir = blockIdx.z;
    const float* W  = dir ? Wb   : Wf;
    const float* b1 = dir ? bihb : bihf;
    const float* b2 = dir ? bhhb : bhhf;

    __shared__ float As[BK][BM];
    __shared__ float Bs[BK][BN];

    int t0 = blockIdx.x * BM;
    int r0 = blockIdx.y * BN;
    int tid = threadIdx.x;           // 256 threads
    int tx = tid & 15;
    int ty = tid >> 4;

    float acc[4][4];
#pragma unroll
    for (int i = 0; i < 4; i++)
#pragma unroll
        for (int j = 0; j < 4; j++) acc[i][j] = 0.f;

    for (int k0 = 0; k0 < D_EMB; k0 += BK) {   // 300 = 25 * 12, no guards
#pragma unroll
        for (int l2 = 0; l2 < 3; l2++) {
            int idx = tid + l2 * 256;       // 0..767
            int row = idx / 12;             // 0..63
            int kk  = idx - row * 12;
            int tg = t0 + row;
            int ts = dir ? (T_LEN - 1 - tg) : tg;
            As[kk][row] = g_x[ts * D_EMB + k0 + kk];
            Bs[kk][row] = W[(r0 + row) * D_EMB + k0 + kk];
        }
        __syncthreads();
#pragma unroll
        for (int kk = 0; kk < BK; kk++) {
            float ra[4], rb[4];
#pragma unroll
            for (int i = 0; i < 4; i++) ra[i] = As[kk][ty * 4 + i];
#pragma unroll
            for (int j = 0; j < 4; j++) rb[j] = Bs[kk][tx * 4 + j];
#pragma unroll
            for (int i = 0; i < 4; i++)
#pragma unroll
                for (int j = 0; j < 4; j++) acc[i][j] += ra[i] * rb[j];
        }
        __syncthreads();
    }

#pragma unroll
    for (int i = 0; i < 4; i++) {
        int t = t0 + ty * 4 + i;
#pragma unroll
        for (int j = 0; j < 4; j++) {
            int r = r0 + tx * 4 + j;
            g_xg[dir][t * G4 + r] = acc[i][j] + b1[r] + b2[r];
        }
    }
}

// ---------------- 3) LSTM recurrence: 8-CTA cluster, P2P release/acquire flags ----------------
// CTA rank owns hidden units [rank*32, rank*32+32). Warp w owns units 2w,2w+1.
// NO barrier.cluster / mbarrier in the step loop. Each producer warp's lanes
// 0-7 store the packed h pair (weak st.shared::cluster.b64) to CTA i, then the
// SAME lane stores its per-warp flag seq=t+1 with st.release.cluster -- the
// release orders the data store before the flag is observable. Each consumer
// lane needs units [8l,8l+8) = 4 specific producer warps of CTA l/4; its 4
// flags are contiguous, polled with 4 scalar ld.acquire.cluster loads in a
// warp-uniform loop (__all_sync). 128 distinct flag words per phase -> no
// serialization point (unlike a central mbarrier). Back-pressure is
// transitive: every warp's step-t flag is data-dependent (via the shuffle
// chain) on its reads of phase-t's buffer, so a producer observing all flags
// of step t+1 proves phase-t buffer/flags are fully consumed before they are
// overwritten at step t+2. u32 seq (not parity) kills ABA; zero-init flags
// pass the step-0 poll (want=0) with the correct zero initial h.
__global__ void __launch_bounds__(512, 1) __cluster_dims__(8, 1, 1)
lstm_kernel8(const float* __restrict__ Whf, const float* __restrict__ Whb) {
    __shared__ float h_buf[2][H_DIM];
    __shared__ uint32_t flags[2][8][16];   // [phase][producer cta][producer warp]

    int dir = blockIdx.y;
    const float* Whh = dir ? Whb : Whf;
    const float* xg = g_xg[dir];
    float* hs = g_hs[dir];

    uint32_t rank;
    asm("mov.u32 %0, %%cluster_ctarank;" : "=r"(rank));

    int tid = threadIdx.x;
    int w = tid >> 5;
    int l = tid & 31;
    int r = (l >> 2) & 7;          // W row this lane finalizes (lane bits 4,3,2)
    int gate = r & 3;
    int du = r >> 2;               // which of the warp's 2 units (== l>>4)
    int xg_col = gate * H_DIM + (int)rank * 32 + 2 * w + du;

    // weight rows q: gate = q&3, unit-offset = q>>2; lane covers k [8l,8l+8)
    unsigned long long w2[8][4];
#pragma unroll
    for (int q = 0; q < 8; q++) {
        int row = (q & 3) * H_DIM + (int)rank * 32 + 2 * w + (q >> 2);
        const float4* p = (const float4*)(Whh + (size_t)row * H_DIM + l * 8);
        float4 a = p[0];
        float4 b = p[1];
        w2[q][0] = pack2(a.x, a.y); w2[q][1] = pack2(a.z, a.w);
        w2[q][2] = pack2(b.x, b.y); w2[q][3] = pack2(b.z, b.w);
    }

    if (tid < 2 * H_DIM) ((float*)h_buf)[tid] = 0.f;
    if (tid < 256) ((uint32_t*)flags)[tid] = 0u;

    uint32_t hb = (uint32_t)__cvta_generic_to_shared(&h_buf[0][0]);
    uint32_t fb = (uint32_t)__cvta_generic_to_shared(&flags[0][0][0]);

    uint32_t rH[8], rF[8];
#pragma unroll
    for (int tg = 0; tg < 8; tg++) {
        asm("mapa.shared::cluster.u32 %0, %1, %2;" : "=r"(rH[tg]) : "r"(hb), "r"(tg));
        asm("mapa.shared::cluster.u32 %0, %1, %2;" : "=r"(rF[tg]) : "r"(fb), "r"(tg));
    }

    __syncthreads();
    // all CTAs' buffers + flags zeroed before any remote traffic
    asm volatile("barrier.cluster.arrive.aligned;" ::: "memory");
    asm volatile("barrier.cluster.wait.aligned;" ::: "memory");

    float c_reg = 0.f;
    float xg_pref = xg[xg_col];    // xg for t=0
    const float LOG2E = 1.4426950408889634f;
    const float act_a = (gate == 2) ? (2.f * LOG2E) : (-LOG2E);
    const bool  is_tanh = (gate == 2);

    // lane-constant poll offset: producer cta l>>2, warps (l&3)*4 .. +3
    uint32_t poll_off = (uint32_t)((((l >> 2) << 4) + ((l & 3) << 2)) * 4);
    // producer flag word for this warp inside each target CTA
    uint32_t pub_off = (uint32_t)(((int)rank * 16 + w) * 4);

#pragma unroll 1
    for (int t = 0; t < T_LEN; t++) {
        int cur = t & 1;
        int nxt = cur ^ 1;

        // wait for the 4 producer warps covering this lane's k-chunk
        {
            uint32_t fa = fb + (uint32_t)cur * 512u + poll_off;
            uint32_t want = (uint32_t)t;
            bool ok;
            do {
                uint32_t f0, f1, f2, f3;
                asm volatile("ld.acquire.cluster.shared::cta.u32 %0, [%1];"
                             : "=r"(f0) : "r"(fa) : "memory");
                asm volatile("ld.acquire.cluster.shared::cta.u32 %0, [%1];"
                             : "=r"(f1) : "r"(fa + 4) : "memory");
                asm volatile("ld.acquire.cluster.shared::cta.u32 %0, [%1];"
                             : "=r"(f2) : "r"(fa + 8) : "memory");
                asm volatile("ld.acquire.cluster.shared::cta.u32 %0, [%1];"
                             : "=r"(f3) : "r"(fa + 12) : "memory");
                ok = (f0 == want) && (f1 == want) && (f2 == want) && (f3 == want);
            } while (!__all_sync(0xffffffffu, ok));
        }

        float4 ha = *(const float4*)&h_buf[cur][l * 8];
        float4 hc = *(const float4*)&h_buf[cur][l * 8 + 4];
        unsigned long long h2[4] = { pack2(ha.x, ha.y), pack2(ha.z, ha.w),
                                     pack2(hc.x, hc.y), pack2(hc.z, hc.w) };

        // next-step xg load issued early (a full step of latency cover)
        float xg_next = 0.f;
        if (t + 1 < T_LEN)
            xg_next = xg[(size_t)(t + 1) * G4 + xg_col];

        float v[8];
#pragma unroll
        for (int q = 0; q < 8; q++) {
            unsigned long long acc = mul2(w2[q][0], h2[0]);
            acc = fma2(w2[q][1], h2[1], acc);
            acc = fma2(w2[q][2], h2[2], acc);
            acc = fma2(w2[q][3], h2[3], acc);
            float lo, hi;
            unpack2(acc, lo, hi);
            v[q] = lo + hi;
        }

        // reduce-scatter onto lane bits 4,3,2 (row = (l>>2)&7)
#pragma unroll
        for (int i = 0; i < 4; i++) {
            float send = (l & 16) ? v[i] : v[i + 4];
            float recv = __shfl_xor_sync(0xffffffffu, send, 16);
            float keep = (l & 16) ? v[i + 4] : v[i];
            v[i] = keep + recv;
        }
#pragma unroll
        for (int i = 0; i < 2; i++) {
            float send = (l & 8) ? v[i] : v[i + 2];
            float recv = __shfl_xor_sync(0xffffffffu, send, 8);
            float keep = (l & 8) ? v[i + 2] : v[i];
            v[i] = keep + recv;
        }
        {
            float send = (l & 4) ? v[0] : v[1];
            float recv = __shfl_xor_sync(0xffffffffu, send, 4);
            float keep = (l & 4) ? v[1] : v[0];
            v[0] = keep + recv;
        }
        // combine the 4 partials living at lane bits 1,0
        float x = v[0];
        x += __shfl_xor_sync(0xffffffffu, x, 1);
        x += __shfl_xor_sync(0xffffffffu, x, 2);

        float pre = x + xg_pref;
        xg_pref = xg_next;

        // branch-free activation: gate 2 -> tanh, else sigmoid (EX2 + RCP)
        float e = exp2f(act_a * pre);
        float z = __fdividef(1.f, 1.f + e);
        float act = is_tanh ? fmaf(-2.f, z, 1.f) : z;

        // gather i,f,g,o for this lane's unit du: rows du*4+g at lanes 16du+4g
        int gbase = du << 4;
        float iv = __shfl_sync(0xffffffffu, act, gbase);
        float fv = __shfl_sync(0xffffffffu, act, gbase + 4);
        float gg = __shfl_sync(0xffffffffu, act, gbase + 8);
        float ov = __shfl_sync(0xffffffffu, act, gbase + 12);

        c_reg = fmaf(fv, c_reg, iv * gg);
        float e2 = exp2f(2.f * LOG2E * c_reg);
        float hval = ov * fmaf(-2.f, __fdividef(1.f, 1.f + e2), 1.f);
        // hval identical within each du half (lanes 0-15: unit 2w; 16-31: 2w+1)

        // single xor-16: every lane obtains the other unit's h
        float h_other = __shfl_xor_sync(0xffffffffu, hval, 16);

        uint32_t off = (uint32_t)((nxt * H_DIM + (int)rank * 32 + 2 * w) * 4);
        uint32_t foff = (uint32_t)nxt * 512u + pub_off;
        uint32_t seq = (uint32_t)(t + 1);
        if (l < 8) {   // lanes 0-7: du=0 -> hval=h0, h_other=h1
            unsigned long long pk = pack2(hval, h_other);
            asm volatile("st.shared::cluster.b64 [%0], %1;"
                         :: "r"(rH[l] + off), "l"(pk) : "memory");
            // release: data store above (same thread) visible before this flag
            asm volatile("st.release.cluster.shared::cluster.u32 [%0], %1;"
                         :: "r"(rF[l] + foff), "r"(seq) : "memory");
        }

        if (l == 8) {  // du=0: hval=h0, h_other=h1
            int tout = dir ? (T_LEN - 1 - t) : t;
            *(float2*)&hs[(size_t)tout * H_DIM + rank * 32 + 2 * w] =
                make_float2(hval, h_other);
        }
    }

    // no CTA may exit while remote stores may still target its smem
    asm volatile("barrier.cluster.arrive.aligned;" ::: "memory");
    asm volatile("barrier.cluster.wait.aligned;" ::: "memory");
}

// ---------------- 4) feats GEMM: [T,512] @ [48,512]^T + b_out ----------------
#define FT_TT 64
__global__ void feats_gemm_kernel(const float* __restrict__ W_out,
                                  const float* __restrict__ b_out) {
    __shared__ float As[32][FT_TT];   // [j][t]
    __shared__ float Bs[32][K_TAGS];  // [j][k]

    int t0 = blockIdx.x * FT_TT;
    int tid = threadIdx.x;            // 256
    int tx = tid & 15;                // k-group: 3 tags
    int ty = tid >> 4;                // t-group: 4 steps

    float acc[4][3];
#pragma unroll
    for (int i = 0; i < 4; i++)
#pragma unroll
        for (int k = 0; k < 3; k++) acc[i][k] = 0.f;

    for (int j0 = 0; j0 < 2 * H_DIM; j0 += 32) {
#pragma unroll
        for (int i = 0; i < 8; i++) {
            int idx = tid + i * 256;        // 0..2047
            int jj = idx & 31;
            int tt = idx >> 5;
            int j = j0 + jj;
            float hv = (j < H_DIM)
                ? g_hs[0][(size_t)(t0 + tt) * H_DIM + j]
                : g_hs[1][(size_t)(t0 + tt) * H_DIM + (j - H_DIM)];
            As[jj][tt] = hv;
        }
        // coalesced W_out load: consecutive threads read consecutive j
#pragma unroll
        for (int i = 0; i < 6; i++) {
            int idx = tid + i * 256;        // 0..1535 = 32 j x 48 k
            int jj = idx & 31;
            int k = idx >> 5;               // 0..47
            Bs[jj][k] = W_out[(size_t)k * (2 * H_DIM) + j0 + jj];
        }
        __syncthreads();
#pragma unroll
        for (int jj = 0; jj < 32; jj++) {
            float a[4], b[3];
#pragma unroll
            for (int i = 0; i < 4; i++) a[i] = As[jj][ty * 4 + i];
#pragma unroll
            for (int k = 0; k < 3; k++) b[k] = Bs[jj][tx * 3 + k];
#pragma unroll
            for (int i = 0; i < 4; i++)
#pragma unroll
                for (int k = 0; k < 3; k++) acc[i][k] += a[i] * b[k];
        }
        __syncthreads();
    }

#pragma unroll
    for (int i = 0; i < 4; i++) {
        int t = t0 + ty * 4 + i;
#pragma unroll
        for (int k = 0; k < 3; k++) {
            int kk = tx * 3 + k;
            g_feats[t * K_TAGS + kk] = acc[i][k] + b_out[kk];
        }
    }
}

// ---------------- 5) Viterbi + backtrace (single CTA, 96 threads, 1 sync/step) ----------------
// Warp w, lane l: tag = w*16 + (l&15), half = l>>4 owns prev range
// [half*24, half*24+24). The two halves of a tag live in the SAME warp and
// combine via shfl_xor(16) with first-index tie-breaking (half0 owns smaller
// prev indices; half1 wins only on strict >). One __syncthreads per step.
#define VIT_SMEM (T_LEN * K_TAGS + 2 * K_TAGS * 4 + 16)
extern __shared__ unsigned char vit_smem[];
__global__ void viterbi_kernel(const float* __restrict__ trans,
                               float* __restrict__ out) {
    unsigned char* bptr = vit_smem;                          // [T][48] u8 = 96KB
    float* fv = (float*)(vit_smem + T_LEN * K_TAGS);         // [2][48]
    int tid = threadIdx.x;  // 96
    int l = tid & 31;
    int wid = tid >> 5;                    // 0..2
    int tag = wid * 16 + (l & 15);
    int half = l >> 4;                     // 0 or 1
    int jlo = half * 24;

    float tr[24];
#pragma unroll
    for (int j = 0; j < 24; j++) tr[j] = trans[tag * K_TAGS + jlo + j];
    if (half == 0) fv[tag] = (tag == START_TAG) ? 0.f : -10000.f;
    float featp = (half == 0) ? g_feats[tag] : 0.f;
    __syncthreads();

    for (int t = 0; t < T_LEN; t++) {
        int cur = (t & 1) * K_TAGS;
        int nxt = K_TAGS - cur;

        // 4 independent max chains over this half's 24 prev-tags
        float b0 = -3.4e38f, b1 = -3.4e38f, b2 = -3.4e38f, b3 = -3.4e38f;
        int a0 = 0, a1 = 1, a2 = 2, a3 = 3;
#pragma unroll
        for (int j = 0; j < 24; j += 4) {
            float s0 = fv[cur + jlo + j]     + tr[j];
            float s1 = fv[cur + jlo + j + 1] + tr[j + 1];
            float s2 = fv[cur + jlo + j + 2] + tr[j + 2];
            float s3 = fv[cur + jlo + j + 3] + tr[j + 3];
            if (s0 > b0) { b0 = s0; a0 = j; }
            if (s1 > b1) { b1 = s1; a1 = j + 1; }
            if (s2 > b2) { b2 = s2; a2 = j + 2; }
            if (s3 > b3) { b3 = s3; a3 = j + 3; }
        }
        float bv = b0; int ba = a0;
        if (b1 > bv || (b1 == bv && a1 < ba)) { bv = b1; ba = a1; }
        if (b2 > bv || (b2 == bv && a2 < ba)) { bv = b2; ba = a2; }
        if (b3 > bv || (b3 == bv && a3 < ba)) { bv = b3; ba = a3; }
        ba += jlo;

        // cross-half combine inside the warp (half0 <-> half1 at xor 16)
        float ov = __shfl_xor_sync(0xffffffffu, bv, 16);
        int   oa = __shfl_xor_sync(0xffffffffu, ba, 16);
        if (half == 0) {
            // strict > : ties keep half0 (smaller prev indices) = jnp.argmax
            if (ov > bv) { bv = ov; ba = oa; }
            fv[nxt + tag] = bv + featp;
            bptr[t * K_TAGS + tag] = (unsigned char)ba;
            if (t + 1 < T_LEN) featp = g_feats[(t + 1) * K_TAGS + tag];
        }
        __syncthreads();
    }

    if (tid == 0) {
        int cur = (T_LEN & 1) * K_TAGS;   // = 0 for even T
        float best = -3.4e38f;
        int btag = 0;
#pragma unroll
        for (int j = 0; j < K_TAGS; j++) {
            float s = fv[cur + j] + trans[STOP_TAG * K_TAGS + j];
            if (s > best) { best = s; btag = j; }
        }
        out[0] = best;
        for (int t = T_LEN - 1; t >= 0; t--) {
            out[1 + t] = (float)btag;
            btag = bptr[t * K_TAGS + btag];
        }
    }
}

// ---------------- launch ----------------
extern "C" void kernel_launch(void* const* d_in, const int* in_sizes, int n_in,
                              void* d_out, int out_size) {
    const int*   sent   = (const int*)d_in[0];
    const float* E      = (const float*)d_in[1];
    const float* W_ih_f = (const float*)d_in[2];
    const float* W_hh_f = (const float*)d_in[3];
    const float* b_ih_f = (const float*)d_in[4];
    const float* b_hh_f = (const float*)d_in[5];
    const float* W_ih_b = (const float*)d_in[6];
    const float* W_hh_b = (const float*)d_in[7];
    const float* b_ih_b = (const float*)d_in[8];
    const float* b_hh_b = (const float*)d_in[9];
    const float* W_out  = (const float*)d_in[10];
    const float* b_out  = (const float*)d_in[11];
    const float* trans  = (const float*)d_in[12];
    float* out = (float*)d_out;

    cudaFuncSetAttribute(viterbi_kernel,
                         cudaFuncAttributeMaxDynamicSharedMemorySize, VIT_SMEM);

    gather_kernel<<<256, 256>>>(sent, E);

    dim3 ggrid(T_LEN / BM, G4 / BN, 2);
    xg_gemm_kernel<<<ggrid, 256>>>(W_ih_f, W_ih_b, b_ih_f, b_hh_f, b_ih_b, b_hh_b);

    lstm_kernel8<<<dim3(8, 2, 1), 512>>>(W_hh_f, W_hh_b);

    feats_gemm_kernel<<<T_LEN / FT_TT, 256>>>(W_out, b_out);

    viterbi_kernel<<<1, 96, VIT_SMEM>>>(trans, out);
}

// round 12
// speedup vs baseline: 1.1981x; 1.1981x over previous
#include <cuda_runtime.h>
#include <cstdint>
#include <math.h>

#define T_LEN  2048
#define D_EMB  300
#define H_DIM  256
#define G4     1024
#define K_TAGS 48
#define START_TAG 46
#define STOP_TAG  47

// ---------------- scratch (device globals; no allocation) ----------------
__device__ float g_xg[2][T_LEN * G4];       // input projections per dir [T, 4H]
__device__ float g_hs[2][T_LEN * H_DIM];    // hidden states per dir, time-aligned
__device__ float g_feats[T_LEN * K_TAGS];   // emission features [T, K]
__device__ int   g_ready[2][32];            // per-(dir, 64-step tile) ready count (16 = full)

// ---------------- f32x2 helpers ----------------
__device__ __forceinline__ unsigned long long pack2(float lo, float hi) {
    unsigned long long r;
    asm("mov.b64 %0, {%1,%2};" : "=l"(r) : "f"(lo), "f"(hi));
    return r;
}
__device__ __forceinline__ void unpack2(unsigned long long v, float& lo, float& hi) {
    asm("mov.b64 {%0,%1}, %2;" : "=f"(lo), "=f"(hi) : "l"(v));
}
__device__ __forceinline__ unsigned long long mul2(unsigned long long a, unsigned long long b) {
    unsigned long long d;
    asm("mul.rn.f32x2 %0, %1, %2;" : "=l"(d) : "l"(a), "l"(b));
    return d;
}
__device__ __forceinline__ unsigned long long fma2(unsigned long long a, unsigned long long b,
                                                   unsigned long long c) {
    unsigned long long d;
    asm("fma.rn.f32x2 %0, %1, %2, %3;" : "=l"(d) : "l"(a), "l"(b), "l"(c));
    return d;
}
__device__ __forceinline__ int ld_acquire_gpu(const int* p) {
    int v;
    asm volatile("ld.acquire.gpu.s32 %0, [%1];" : "=r"(v) : "l"(p) : "memory");
    return v;
}

// ================= MEGA KERNEL: xg-GEMM workers + LSTM clusters =================
// grid (8, 18), cluster (8,1,1), 512 threads.
//  y < 2  : LSTM 8-CTA cluster for direction y (frozen champion protocol).
//  y >= 2 : 128 worker CTAs computing xg = gather(E,sent) @ W_ih^T + b_ih + b_hh
//           for BOTH dirs. 1024 tiles (64t x 64r), enumerated t-tile-major so
//           early timesteps complete first. Each finished tile bumps
//           g_ready[dir][ttile] (16 r-tiles per (dir,ttile) = full).
//  LSTM polls its dir's tile counter once per 64 steps (tid 0 + syncthreads),
//  and resets its dir's counters to 0 at kernel end (replay-safe).
__global__ void __launch_bounds__(512, 1) __cluster_dims__(8, 1, 1)
mega_kernel(const int* __restrict__ sent, const float* __restrict__ E,
            const float* __restrict__ Wihf, const float* __restrict__ Whhf,
            const float* __restrict__ bihf, const float* __restrict__ bhhf,
            const float* __restrict__ Wihb, const float* __restrict__ Whhb,
            const float* __restrict__ bihb, const float* __restrict__ bhhb) {
    __shared__ float h_buf[2][H_DIM];
    __shared__ float As[12][64];
    __shared__ float Bs[12][64];

    int tid = threadIdx.x;

    if (blockIdx.y >= 2) {
        // ---------------- xg-GEMM worker role ----------------
        int worker = (int)(blockIdx.y - 2) * 8 + (int)blockIdx.x;   // 0..127
#pragma unroll 1
        for (int pass = 0; pass < 8; pass++) {
            int tile = worker + pass * 128;      // 0..1023, t-tile-major
            int ttile = tile >> 5;
            int rem = tile & 31;
            int rtile = rem >> 1;
            int dir = rem & 1;
            int t0 = ttile * 64;
            int r0 = rtile * 64;
            const float* Wih = dir ? Wihb : Wihf;
            const float* b1 = dir ? bihb : bihf;
            const float* b2 = dir ? bhhb : bhhf;

            int tx = tid & 15;       // 4 output cols
            int ty = tid >> 4;       // 32 groups of 2 output rows (time)
            float acc[2][4];
#pragma unroll
            for (int i = 0; i < 2; i++)
#pragma unroll
                for (int j = 0; j < 4; j++) acc[i][j] = 0.f;

            for (int k0 = 0; k0 < D_EMB; k0 += 12) {
#pragma unroll
                for (int l2 = 0; l2 < 2; l2++) {
                    int idx = tid + l2 * 512;
                    if (idx < 768) {
                        int row = idx / 12;
                        int kk = idx - row * 12;
                        int tg = t0 + row;
                        int ts = dir ? (T_LEN - 1 - tg) : tg;
                        long long vrow = sent[ts];
                        As[kk][row] = E[vrow * D_EMB + k0 + kk];
                        Bs[kk][row] = Wih[(size_t)(r0 + row) * D_EMB + k0 + kk];
                    }
                }
                __syncthreads();
#pragma unroll
                for (int kk = 0; kk < 12; kk++) {
                    float ra0 = As[kk][ty * 2];
                    float ra1 = As[kk][ty * 2 + 1];
                    float rb[4];
#pragma unroll
                    for (int j = 0; j < 4; j++) rb[j] = Bs[kk][tx * 4 + j];
#pragma unroll
                    for (int j = 0; j < 4; j++) {
                        acc[0][j] += ra0 * rb[j];
                        acc[1][j] += ra1 * rb[j];
                    }
                }
                __syncthreads();
            }

#pragma unroll
            for (int i = 0; i < 2; i++) {
                int t = t0 + ty * 2 + i;
#pragma unroll
                for (int j = 0; j < 4; j++) {
                    int r = r0 + tx * 4 + j;
                    g_xg[dir][(size_t)t * G4 + r] = acc[i][j] + b1[r] + b2[r];
                }
            }
            __syncthreads();
            __threadfence();
            if (tid == 0) atomicAdd(&g_ready[dir][ttile], 1);
        }
        return;
    }

    // ---------------- LSTM cluster role (frozen champion) ----------------
    int dir = blockIdx.y;
    const float* Whh = dir ? Whhb : Whhf;
    const float* xg = g_xg[dir];
    float* hs = g_hs[dir];

    uint32_t rank;
    asm("mov.u32 %0, %%cluster_ctarank;" : "=r"(rank));

    int w = tid >> 5;
    int l = tid & 31;
    int r = (l >> 2) & 7;          // W row this lane finalizes (lane bits 4,3,2)
    int gate = r & 3;
    int du = r >> 2;               // which of the warp's 2 units (== l>>4)
    int xg_col = gate * H_DIM + (int)rank * 32 + 2 * w + du;

    unsigned long long w2[8][4];
#pragma unroll
    for (int q = 0; q < 8; q++) {
        int row = (q & 3) * H_DIM + (int)rank * 32 + 2 * w + (q >> 2);
        const float4* p = (const float4*)(Whh + (size_t)row * H_DIM + l * 8);
        float4 a = p[0];
        float4 b = p[1];
        w2[q][0] = pack2(a.x, a.y); w2[q][1] = pack2(a.z, a.w);
        w2[q][2] = pack2(b.x, b.y); w2[q][3] = pack2(b.z, b.w);
    }

    if (tid < 2 * H_DIM) ((float*)h_buf)[tid] = 0.f;
    uint32_t hb = (uint32_t)__cvta_generic_to_shared(&h_buf[0][0]);

    uint32_t rH[8];
#pragma unroll
    for (int tg = 0; tg < 8; tg++) {
        asm("mapa.shared::cluster.u32 %0, %1, %2;" : "=r"(rH[tg]) : "r"(hb), "r"(tg));
    }

    __syncthreads();
    asm volatile("barrier.cluster.arrive.aligned;" ::: "memory");
    asm volatile("barrier.cluster.wait.aligned;" ::: "memory");

    // wait for xg tile 0 of this direction
    if (tid == 0) {
        while (ld_acquire_gpu(&g_ready[dir][0]) < 16) {}
    }
    __syncthreads();

    float c_reg = 0.f;
    float xg_pref = xg[xg_col];    // xg for t=0
    const float LOG2E = 1.4426950408889634f;
    const float act_a = (gate == 2) ? (2.f * LOG2E) : (-LOG2E);
    const bool  is_tanh = (gate == 2);

#pragma unroll 1
    for (int t = 0; t < T_LEN; t++) {
        int cur = t & 1;
        int nxt = cur ^ 1;

        // prefetch of xg[t+1] during this step crosses into tile (t+1)>>6
        if ((t & 63) == 63 && t + 1 < T_LEN) {
            if (tid == 0) {
                int need = (t + 1) >> 6;
                while (ld_acquire_gpu(&g_ready[dir][need]) < 16) {}
            }
            __syncthreads();
        }

        float4 ha = *(const float4*)&h_buf[cur][l * 8];
        float4 hc = *(const float4*)&h_buf[cur][l * 8 + 4];
        unsigned long long h2[4] = { pack2(ha.x, ha.y), pack2(ha.z, ha.w),
                                     pack2(hc.x, hc.y), pack2(hc.z, hc.w) };
        float v[8];
#pragma unroll
        for (int q = 0; q < 8; q++) {
            unsigned long long acc = mul2(w2[q][0], h2[0]);
            acc = fma2(w2[q][1], h2[1], acc);
            acc = fma2(w2[q][2], h2[2], acc);
            acc = fma2(w2[q][3], h2[3], acc);
            float lo, hi;
            unpack2(acc, lo, hi);
            v[q] = lo + hi;
        }

        // reduce-scatter onto lane bits 4,3,2 (row = (l>>2)&7)
#pragma unroll
        for (int i = 0; i < 4; i++) {
            float send = (l & 16) ? v[i] : v[i + 4];
            float recv = __shfl_xor_sync(0xffffffffu, send, 16);
            float keep = (l & 16) ? v[i + 4] : v[i];
            v[i] = keep + recv;
        }
#pragma unroll
        for (int i = 0; i < 2; i++) {
            float send = (l & 8) ? v[i] : v[i + 2];
            float recv = __shfl_xor_sync(0xffffffffu, send, 8);
            float keep = (l & 8) ? v[i + 2] : v[i];
            v[i] = keep + recv;
        }
        {
            float send = (l & 4) ? v[0] : v[1];
            float recv = __shfl_xor_sync(0xffffffffu, send, 4);
            float keep = (l & 4) ? v[1] : v[0];
            v[0] = keep + recv;
        }
        // combine the 4 partials living at lane bits 1,0
        float x = v[0];
        x += __shfl_xor_sync(0xffffffffu, x, 1);
        x += __shfl_xor_sync(0xffffffffu, x, 2);

        float pre = x + xg_pref;

        // branch-free activation: gate 2 -> tanh, else sigmoid (EX2 + RCP)
        float e = exp2f(act_a * pre);
        float z = __fdividef(1.f, 1.f + e);
        float act = is_tanh ? fmaf(-2.f, z, 1.f) : z;

        // gather i,f,g,o for this lane's unit du: rows du*4+g at lanes 16du+4g
        int gbase = du << 4;
        float iv = __shfl_sync(0xffffffffu, act, gbase);
        float fv = __shfl_sync(0xffffffffu, act, gbase + 4);
        float gg = __shfl_sync(0xffffffffu, act, gbase + 8);
        float ov = __shfl_sync(0xffffffffu, act, gbase + 12);

        c_reg = fmaf(fv, c_reg, iv * gg);
        float e2 = exp2f(2.f * LOG2E * c_reg);
        float hval = ov * fmaf(-2.f, __fdividef(1.f, 1.f + e2), 1.f);
        // hval identical within each du half (lanes 0-15: unit 2w; 16-31: 2w+1)

        // single xor-16: every lane obtains the other unit's h
        float h_other = __shfl_xor_sync(0xffffffffu, hval, 16);

        uint32_t off = (uint32_t)((nxt * H_DIM + (int)rank * 32 + 2 * w) * 4);
        if (l < 8) {   // lanes 0-7: du=0 -> hval=h0, h_other=h1
            unsigned long long pk = pack2(hval, h_other);
            asm volatile("st.shared::cluster.b64 [%0], %1;"
                         :: "r"(rH[l] + off), "l"(pk) : "memory");
        }

        asm volatile("barrier.cluster.arrive.aligned;" ::: "memory");

        // issue next-step xg load inside the barrier window (latency hidden)
        if (t + 1 < T_LEN)
            xg_pref = xg[(size_t)(t + 1) * G4 + xg_col];

        if (l == 8) {  // du=0: hval=h0, h_other=h1
            int tout = dir ? (T_LEN - 1 - t) : t;
            *(float2*)&hs[(size_t)tout * H_DIM + rank * 32 + 2 * w] =
                make_float2(hval, h_other);
        }

        asm volatile("barrier.cluster.wait.aligned;" ::: "memory");
    }

    asm volatile("barrier.cluster.arrive.aligned;" ::: "memory");
    asm volatile("barrier.cluster.wait.aligned;" ::: "memory");

    // reset this dir's ready counters for the next graph replay
    if (rank == 0 && tid < 32) g_ready[dir][tid] = 0;
}

// ---------------- feats GEMM: [T,512] @ [48,512]^T + b_out ----------------
#define FT_TT 64
__global__ void feats_gemm_kernel(const float* __restrict__ W_out,
                                  const float* __restrict__ b_out) {
    __shared__ float As[32][FT_TT];   // [j][t]
    __shared__ float Bs[32][K_TAGS];  // [j][k]

    int t0 = blockIdx.x * FT_TT;
    int tid = threadIdx.x;            // 256
    int tx = tid & 15;                // k-group: 3 tags
    int ty = tid >> 4;                // t-group: 4 steps

    float acc[4][3];
#pragma unroll
    for (int i = 0; i < 4; i++)
#pragma unroll
        for (int k = 0; k < 3; k++) acc[i][k] = 0.f;

    for (int j0 = 0; j0 < 2 * H_DIM; j0 += 32) {
#pragma unroll
        for (int i = 0; i < 8; i++) {
            int idx = tid + i * 256;        // 0..2047
            int jj = idx & 31;
            int tt = idx >> 5;
            int j = j0 + jj;
            float hv = (j < H_DIM)
                ? g_hs[0][(size_t)(t0 + tt) * H_DIM + j]
                : g_hs[1][(size_t)(t0 + tt) * H_DIM + (j - H_DIM)];
            As[jj][tt] = hv;
        }
        // coalesced W_out load: consecutive threads read consecutive j
#pragma unroll
        for (int i = 0; i < 6; i++) {
            int idx = tid + i * 256;        // 0..1535 = 32 j x 48 k
            int jj = idx & 31;
            int k = idx >> 5;               // 0..47
            Bs[jj][k] = W_out[(size_t)k * (2 * H_DIM) + j0 + jj];
        }
        __syncthreads();
#pragma unroll
        for (int jj = 0; jj < 32; jj++) {
            float a[4], b[3];
#pragma unroll
            for (int i = 0; i < 4; i++) a[i] = As[jj][ty * 4 + i];
#pragma unroll
            for (int k = 0; k < 3; k++) b[k] = Bs[jj][tx * 3 + k];
#pragma unroll
            for (int i = 0; i < 4; i++)
#pragma unroll
                for (int k = 0; k < 3; k++) acc[i][k] += a[i] * b[k];
        }
        __syncthreads();
    }

#pragma unroll
    for (int i = 0; i < 4; i++) {
        int t = t0 + ty * 4 + i;
#pragma unroll
        for (int k = 0; k < 3; k++) {
            int kk = tx * 3 + k;
            g_feats[t * K_TAGS + kk] = acc[i][k] + b_out[kk];
        }
    }
}

// ---------------- Viterbi + backtrace (single CTA, 96 threads, 1 sync/step) ----------------
// Warp w, lane l: tag = w*16 + (l&15), half = l>>4 owns prev range
// [half*24, half*24+24). Halves combine via shfl_xor(16) with first-index
// tie-breaking. fv loads vectorized as 6 x LDS.128 per thread per step.
#define VIT_SMEM (T_LEN * K_TAGS + 2 * K_TAGS * 4 + 16)
extern __shared__ unsigned char vit_smem[];
__global__ void viterbi_kernel(const float* __restrict__ trans,
                               float* __restrict__ out) {
    unsigned char* bptr = vit_smem;                          // [T][48] u8 = 96KB
    float* fv = (float*)(vit_smem + T_LEN * K_TAGS);         // [2][48], 16B aligned
    int tid = threadIdx.x;  // 96
    int l = tid & 31;
    int wid = tid >> 5;                    // 0..2
    int tag = wid * 16 + (l & 15);
    int half = l >> 4;                     // 0 or 1
    int jlo = half * 24;

    float tr[24];
#pragma unroll
    for (int j = 0; j < 24; j++) tr[j] = trans[tag * K_TAGS + jlo + j];
    if (half == 0) fv[tag] = (tag == START_TAG) ? 0.f : -10000.f;
    float featp = (half == 0) ? g_feats[tag] : 0.f;
    __syncthreads();

    for (int t = 0; t < T_LEN; t++) {
        int cur = (t & 1) * K_TAGS;
        int nxt = K_TAGS - cur;

        // vectorized fv load: 24 floats = 6 x float4 (all 16B aligned)
        float vals[24];
        {
            const float4* fp = (const float4*)&fv[cur + jlo];
#pragma unroll
            for (int q = 0; q < 6; q++)
                *(float4*)&vals[q * 4] = fp[q];
        }

        // 4 independent max chains over this half's 24 prev-tags
        float b0 = -3.4e38f, b1 = -3.4e38f, b2 = -3.4e38f, b3 = -3.4e38f;
        int a0 = 0, a1 = 1, a2 = 2, a3 = 3;
#pragma unroll
        for (int j = 0; j < 24; j += 4) {
            float s0 = vals[j]     + tr[j];
            float s1 = vals[j + 1] + tr[j + 1];
            float s2 = vals[j + 2] + tr[j + 2];
            float s3 = vals[j + 3] + tr[j + 3];
            if (s0 > b0) { b0 = s0; a0 = j; }
            if (s1 > b1) { b1 = s1; a1 = j + 1; }
            if (s2 > b2) { b2 = s2; a2 = j + 2; }
            if (s3 > b3) { b3 = s3; a3 = j + 3; }
        }
        float bv = b0; int ba = a0;
        if (b1 > bv || (b1 == bv && a1 < ba)) { bv = b1; ba = a1; }
        if (b2 > bv || (b2 == bv && a2 < ba)) { bv = b2; ba = a2; }
        if (b3 > bv || (b3 == bv && a3 < ba)) { bv = b3; ba = a3; }
        ba += jlo;

        // cross-half combine inside the warp (half0 <-> half1 at xor 16)
        float ov = __shfl_xor_sync(0xffffffffu, bv, 16);
        int   oa = __shfl_xor_sync(0xffffffffu, ba, 16);
        if (half == 0) {
            // strict > : ties keep half0 (smaller prev indices) = jnp.argmax
            if (ov > bv) { bv = ov; ba = oa; }
            fv[nxt + tag] = bv + featp;
            bptr[t * K_TAGS + tag] = (unsigned char)ba;
            if (t + 1 < T_LEN) featp = g_feats[(t + 1) * K_TAGS + tag];
        }
        __syncthreads();
    }

    if (tid == 0) {
        int cur = (T_LEN & 1) * K_TAGS;   // = 0 for even T
        float best = -3.4e38f;
        int btag = 0;
#pragma unroll
        for (int j = 0; j < K_TAGS; j++) {
            float s = fv[cur + j] + trans[STOP_TAG * K_TAGS + j];
            if (s > best) { best = s; btag = j; }
        }
        out[0] = best;
        for (int t = T_LEN - 1; t >= 0; t--) {
            out[1 + t] = (float)btag;
            btag = bptr[t * K_TAGS + btag];
        }
    }
}

// ---------------- launch ----------------
extern "C" void kernel_launch(void* const* d_in, const int* in_sizes, int n_in,
                              void* d_out, int out_size) {
    const int*   sent   = (const int*)d_in[0];
    const float* E      = (const float*)d_in[1];
    const float* W_ih_f = (const float*)d_in[2];
    const float* W_hh_f = (const float*)d_in[3];
    const float* b_ih_f = (const float*)d_in[4];
    const float* b_hh_f = (const float*)d_in[5];
    const float* W_ih_b = (const float*)d_in[6];
    const float* W_hh_b = (const float*)d_in[7];
    const float* b_ih_b = (const float*)d_in[8];
    const float* b_hh_b = (const float*)d_in[9];
    const float* W_out  = (const float*)d_in[10];
    const float* b_out  = (const float*)d_in[11];
    const float* trans  = (const float*)d_in[12];
    float* out = (float*)d_out;

    cudaFuncSetAttribute(viterbi_kernel,
                         cudaFuncAttributeMaxDynamicSharedMemorySize, VIT_SMEM);

    // gather + xg GEMM + both LSTM directions in ONE launch:
    // y<2 = LSTM clusters, y>=2 = 128 GEMM worker CTAs (flag-synced).
    mega_kernel<<<dim3(8, 18, 1), 512>>>(sent, E,
                                         W_ih_f, W_hh_f, b_ih_f, b_hh_f,
                                         W_ih_b, W_hh_b, b_ih_b, b_hh_b);

    feats_gemm_kernel<<<T_LEN / FT_TT, 256>>>(W_out, b_out);

    viterbi_kernel<<<1, 96, VIT_SMEM>>>(trans, out);
}